// round 14
// baseline (speedup 1.0000x reference)
#include <cuda_runtime.h>
#include <cuda_fp16.h>
#include <cstdint>
#include <cmath>

#define BATCH 8
#define SEQ   2048
#define DIM   512
#define MROWS (BATCH * SEQ)   // 16384

// -------- fp16 scratch (allocation-free) --------
__device__ __half g_Xh[MROWS * DIM];
__device__ __half g_Wqh[DIM * DIM];
__device__ __half g_Wkh[DIM * DIM];
__device__ __half g_Wvh[DIM * DIM];
__device__ __half g_Qh[MROWS * DIM];
__device__ __half g_Kh[MROWS * DIM];
__device__ __half g_Vth[BATCH * DIM * SEQ];
__device__ __half g_Wth[(size_t)BATCH * SEQ * SEQ];

// -------- tiling --------
#define BK 64
#define TILE_B  16384                       // 128 rows x 64 f16 (128 B/row)
#define STAGES  3
#define STAGE_B (2 * TILE_B)                // A + B
#define SMEM_BYTES (STAGES * STAGE_B)       // 98304
#define OFF_B   16384

// ================= PTX helpers =================
__device__ __forceinline__ uint32_t smem_u32(const void* p) {
    uint32_t a;
    asm("{ .reg .u64 t; cvta.to.shared.u64 t, %1; cvt.u32.u64 %0, t; }" : "=r"(a) : "l"(p));
    return a;
}
__device__ __forceinline__ void cp16(uint32_t dst, const void* src) {
    asm volatile("cp.async.cg.shared.global [%0], [%1], 16;" :: "r"(dst), "l"(src));
}
#define CP_COMMIT() asm volatile("cp.async.commit_group;" ::: "memory")
#define CP_WAIT1()  asm volatile("cp.async.wait_group 1;" ::: "memory")

__device__ __forceinline__ void ldm4(uint32_t* d, uint32_t addr) {
    asm volatile("ldmatrix.sync.aligned.m8n8.x4.shared.b16 {%0,%1,%2,%3}, [%4];"
        : "=r"(d[0]), "=r"(d[1]), "=r"(d[2]), "=r"(d[3]) : "r"(addr));
}
__device__ __forceinline__ void mma16(float* d, const uint32_t* a, uint32_t b0, uint32_t b1) {
    asm volatile("mma.sync.aligned.m16n8k16.row.col.f32.f16.f16.f32 "
        "{%0,%1,%2,%3}, {%4,%5,%6,%7}, {%8,%9}, {%0,%1,%2,%3};"
        : "+f"(d[0]), "+f"(d[1]), "+f"(d[2]), "+f"(d[3])
        : "r"(a[0]), "r"(a[1]), "r"(a[2]), "r"(a[3]), "r"(b0), "r"(b1));
}

// 128x64 f16 tile: row r at r*128; chunk c rotated: r*128 + ((c+r)&7)*16.
__device__ __forceinline__ uint32_t tile_addr(uint32_t base, int r, int c) {
    return base + (uint32_t)((r << 7) + ((((c + r) & 7)) << 4));
}

// Producer: 128x64 f16 tile, 1024 chunks, 4 per thread.
__device__ __forceinline__ void load_tile(uint32_t sdst, const __half* __restrict__ src,
                                          int ld, int kt, int tid)
{
    #pragma unroll
    for (int i = 0; i < 4; i++) {
        int ch = tid + i * 256;
        int r = ch >> 3, c = ch & 7;
        cp16(tile_addr(sdst, r, c), src + (size_t)r * ld + kt + c * 8);
    }
}

// ================= GEMM mainloop (BK=64, 3 stages) =================
__device__ __forceinline__ void gemm1_main(
    const __half* __restrict__ Ah, int lda,
    const __half* __restrict__ Bh, int ldb,
    int ktot, float (&acc)[2][8][4], char* smem, int tid)
{
    const int wid = tid >> 5, lane = tid & 31;
    const int wm = (wid & 3) * 32, wn = (wid >> 2) * 64;
    const int q = lane >> 3;
    const int lrow = (lane & 7) + (q & 1) * 8;
    const int qc = q >> 1;
    const uint32_t sbase = smem_u32(smem);
    const int NK = ktot / BK;

    int pf = 0, wrs = 0;
    #pragma unroll
    for (int s = 0; s < STAGES - 1; s++) {
        if (pf < NK) {
            uint32_t sp = sbase + (uint32_t)wrs * STAGE_B;
            load_tile(sp, Ah, lda, pf * BK, tid);
            load_tile(sp + OFF_B, Bh, ldb, pf * BK, tid);
            CP_COMMIT();
            pf++; wrs = (wrs == STAGES - 1) ? 0 : wrs + 1;
        }
    }

    int rds = 0;
    for (int kb = 0; kb < NK; kb++) {
        CP_WAIT1();
        __syncthreads();
        const uint32_t st = sbase + (uint32_t)rds * STAGE_B;
        rds = (rds == STAGES - 1) ? 0 : rds + 1;

        if (pf < NK) {
            uint32_t sp = sbase + (uint32_t)wrs * STAGE_B;
            load_tile(sp, Ah, lda, pf * BK, tid);
            load_tile(sp + OFF_B, Bh, ldb, pf * BK, tid);
            CP_COMMIT();
            pf++; wrs = (wrs == STAGES - 1) ? 0 : wrs + 1;
        } else {
            CP_COMMIT();
        }

        #pragma unroll
        for (int ks = 0; ks < 4; ks++) {
            const int c = 2 * ks + qc;
            uint32_t ah[2][4];
            #pragma unroll
            for (int mt = 0; mt < 2; mt++)
                ldm4(ah[mt], tile_addr(st, wm + mt * 16 + lrow, c));
            uint32_t bh[4][4];
            #pragma unroll
            for (int nb = 0; nb < 4; nb++)
                ldm4(bh[nb], tile_addr(st + OFF_B, wn + nb * 16 + lrow, c));
            #pragma unroll
            for (int mt = 0; mt < 2; mt++)
                #pragma unroll
                for (int nb = 0; nb < 4; nb++) {
                    mma16(acc[mt][nb * 2 + 0], ah[mt], bh[nb][0], bh[nb][2]);
                    mma16(acc[mt][nb * 2 + 1], ah[mt], bh[nb][1], bh[nb][3]);
                }
        }
        // no trailing sync: top-of-loop barrier provides the WAR guarantee.
    }
}

// ================= kernels =================
__global__ __launch_bounds__(256) void cvt_x_kernel(const float* __restrict__ src)
{
    int i = blockIdx.x * 256 + threadIdx.x;
    float4 v = ((const float4*)src)[i];
    ((__half2*)g_Xh)[i * 2]     = __halves2half2(__float2half_rn(v.x), __float2half_rn(v.y));
    ((__half2*)g_Xh)[i * 2 + 1] = __halves2half2(__float2half_rn(v.z), __float2half_rn(v.w));
}
__global__ __launch_bounds__(256) void cvt_w_kernel(
    const float* __restrict__ Wq, const float* __restrict__ Wk, const float* __restrict__ Wv)
{
    const float* src = blockIdx.z == 0 ? Wq : (blockIdx.z == 1 ? Wk : Wv);
    __half* h = blockIdx.z == 0 ? g_Wqh : (blockIdx.z == 1 ? g_Wkh : g_Wvh);
    int i = blockIdx.x * 256 + threadIdx.x;
    float4 v = ((const float4*)src)[i];
    ((__half2*)h)[i * 2]     = __halves2half2(__float2half_rn(v.x), __float2half_rn(v.y));
    ((__half2*)h)[i * 2 + 1] = __halves2half2(__float2half_rn(v.z), __float2half_rn(v.w));
}

// Q/K projection (Xh·Wh + b) -> fp16
__global__ __launch_bounds__(256, 2) void qk_proj_kernel(
    const float* __restrict__ bq, const float* __restrict__ bk)
{
    extern __shared__ char smem[];
    const int tid = threadIdx.x, wid = tid >> 5, lane = tid & 31;
    const int g = lane >> 2, tg = lane & 3;
    const int m0 = blockIdx.y * 128, n0 = blockIdx.x * 128;
    const bool isk = blockIdx.z != 0;
    const __half* Wh = isk ? g_Wkh : g_Wqh;
    const float* bias = isk ? bk : bq;
    __half* Oh = isk ? g_Kh : g_Qh;

    float acc[2][8][4] = {};
    gemm1_main(g_Xh + (size_t)m0 * DIM, DIM, Wh + (size_t)n0 * DIM, DIM,
               DIM, acc, smem, tid);

    const int wm = (wid & 3) * 32, wn = (wid >> 2) * 64;
    #pragma unroll
    for (int mt = 0; mt < 2; mt++) {
        int m = m0 + wm + mt * 16 + g;
        #pragma unroll
        for (int nt = 0; nt < 8; nt++) {
            int n = n0 + wn + nt * 8 + tg * 2;
            float b0 = bias[n], b1 = bias[n + 1];
            *(__half2*)&Oh[(size_t)m * DIM + n] =
                __halves2half2(__float2half_rn(acc[mt][nt][0] + b0),
                               __float2half_rn(acc[mt][nt][1] + b1));
            *(__half2*)&Oh[(size_t)(m + 8) * DIM + n] =
                __halves2half2(__float2half_rn(acc[mt][nt][2] + b0),
                               __float2half_rn(acc[mt][nt][3] + b1));
        }
    }
}

// V projection transposed (Wvh·Xh + bv) -> Vt fp16
__global__ __launch_bounds__(256, 2) void v_proj_kernel(const float* __restrict__ bv)
{
    extern __shared__ char smem[];
    const int tid = threadIdx.x, wid = tid >> 5, lane = tid & 31;
    const int g = lane >> 2, tg = lane & 3;
    const int m0 = blockIdx.y * 128, n0 = blockIdx.x * 128;

    float acc[2][8][4] = {};
    gemm1_main(g_Wvh + (size_t)m0 * DIM, DIM, g_Xh + (size_t)n0 * DIM, DIM,
               DIM, acc, smem, tid);

    const int wm = (wid & 3) * 32, wn = (wid >> 2) * 64;
    const int b = n0 >> 11;
    #pragma unroll
    for (int mt = 0; mt < 2; mt++) {
        int e = m0 + wm + mt * 16 + g;
        float be0 = bv[e], be1 = bv[e + 8];
        #pragma unroll
        for (int nt = 0; nt < 8; nt++) {
            int t = n0 + wn + nt * 8 + tg * 2;
            int s = t & 2047;
            __half2 h = __halves2half2(__float2half_rn(acc[mt][nt][0] + be0),
                                       __float2half_rn(acc[mt][nt][1] + be0));
            *(__half2*)&g_Vth[((size_t)b * DIM + e) * SEQ + s] = h;
            h = __halves2half2(__float2half_rn(acc[mt][nt][2] + be1),
                               __float2half_rn(acc[mt][nt][3] + be1));
            *(__half2*)&g_Vth[((size_t)b * DIM + e + 8) * SEQ + s] = h;
        }
    }
}

// scores for ONE batch (Qh·Kh; masked, fp32 out)
__global__ __launch_bounds__(256, 2) void scores_kernel(
    const int* __restrict__ mask, float* __restrict__ out_w, float scale, int b)
{
    extern __shared__ char smem[];
    const int tid = threadIdx.x, wid = tid >> 5, lane = tid & 31;
    const int g = lane >> 2, tg = lane & 3;
    const int m0 = blockIdx.y * 128, n0 = blockIdx.x * 128;
    const size_t qoff = ((size_t)b * SEQ + m0) * DIM;
    const size_t koff = ((size_t)b * SEQ + n0) * DIM;

    float acc[2][8][4] = {};
    gemm1_main(g_Qh + qoff, DIM, g_Kh + koff, DIM, DIM, acc, smem, tid);

    const int wm = (wid & 3) * 32, wn = (wid >> 2) * 64;
    const size_t base = (size_t)b * SEQ * SEQ;
    #pragma unroll
    for (int mt = 0; mt < 2; mt++) {
        int qq = m0 + wm + mt * 16 + g;
        #pragma unroll
        for (int nt = 0; nt < 8; nt++) {
            int n = n0 + wn + nt * 8 + tg * 2;
            size_t i0 = base + (size_t)qq * SEQ + n;
            size_t i1 = base + (size_t)(qq + 8) * SEQ + n;
            int2 mk0 = *(const int2*)&mask[i0];
            int2 mk1 = *(const int2*)&mask[i1];
            *(float2*)&out_w[i0] = make_float2(mk0.x ? acc[mt][nt][0] * scale : -1e9f,
                                              mk0.y ? acc[mt][nt][1] * scale : -1e9f);
            *(float2*)&out_w[i1] = make_float2(mk1.x ? acc[mt][nt][2] * scale : -1e9f,
                                              mk1.y ? acc[mt][nt][3] * scale : -1e9f);
        }
    }
}

// softmax for ONE batch: in place (fp32) + fp16 copy
__global__ __launch_bounds__(256) void softmax_kernel(
    float* __restrict__ W, __half* __restrict__ Wh, int b)
{
    const size_t rowb = ((size_t)b * SEQ + blockIdx.x) * SEQ;
    float4* p = (float4*)(W + rowb);
    __half2* ph = (__half2*)(Wh + rowb);
    const int tid = threadIdx.x;

    float4 v[2];
    float m = -INFINITY;
    #pragma unroll
    for (int i = 0; i < 2; i++) {
        v[i] = p[tid + i * 256];
        m = fmaxf(m, fmaxf(fmaxf(v[i].x, v[i].y), fmaxf(v[i].z, v[i].w)));
    }
    __shared__ float red[256];
    red[tid] = m; __syncthreads();
    #pragma unroll
    for (int s = 128; s > 0; s >>= 1) { if (tid < s) red[tid] = fmaxf(red[tid], red[tid + s]); __syncthreads(); }
    m = red[0]; __syncthreads();

    float sum = 0.0f;
    #pragma unroll
    for (int i = 0; i < 2; i++) {
        v[i].x = __expf(v[i].x - m); v[i].y = __expf(v[i].y - m);
        v[i].z = __expf(v[i].z - m); v[i].w = __expf(v[i].w - m);
        sum += v[i].x + v[i].y + v[i].z + v[i].w;
    }
    red[tid] = sum; __syncthreads();
    #pragma unroll
    for (int s = 128; s > 0; s >>= 1) { if (tid < s) red[tid] += red[tid + s]; __syncthreads(); }
    float inv = 1.0f / red[0];

    #pragma unroll
    for (int i = 0; i < 2; i++) {
        int j = tid + i * 256;
        v[i].x *= inv; v[i].y *= inv; v[i].z *= inv; v[i].w *= inv;
        p[j] = v[i];
        ph[j * 2]     = __halves2half2(__float2half_rn(v[i].x), __float2half_rn(v[i].y));
        ph[j * 2 + 1] = __halves2half2(__float2half_rn(v[i].z), __float2half_rn(v[i].w));
    }
}

// out for ONE batch: C[q][d] = Wgt_h[q]·Vt_h[d]
__global__ __launch_bounds__(256, 2) void out_kernel(float* __restrict__ O, int b)
{
    extern __shared__ char smem[];
    const int tid = threadIdx.x, wid = tid >> 5, lane = tid & 31;
    const int g = lane >> 2, tg = lane & 3;
    const int m0 = blockIdx.y * 128, n0 = blockIdx.x * 128;
    const size_t aoff = (size_t)b * SEQ * SEQ + (size_t)m0 * SEQ;
    const size_t boff = (size_t)b * DIM * SEQ + (size_t)n0 * SEQ;

    float acc[2][8][4] = {};
    gemm1_main(g_Wth + aoff, SEQ, g_Vth + boff, SEQ, SEQ, acc, smem, tid);

    const int wm = (wid & 3) * 32, wn = (wid >> 2) * 64;
    float* Ob = O + (size_t)b * SEQ * DIM;
    #pragma unroll
    for (int mt = 0; mt < 2; mt++) {
        int qq = m0 + wm + mt * 16 + g;
        #pragma unroll
        for (int nt = 0; nt < 8; nt++) {
            int n = n0 + wn + nt * 8 + tg * 2;
            *(float2*)&Ob[(size_t)qq * DIM + n] = make_float2(acc[mt][nt][0], acc[mt][nt][1]);
            *(float2*)&Ob[(size_t)(qq + 8) * DIM + n] = make_float2(acc[mt][nt][2], acc[mt][nt][3]);
        }
    }
}

// ================= launch =================
extern "C" void kernel_launch(void* const* d_in, const int* in_sizes, int n_in,
                              void* d_out, int out_size)
{
    const float* X  = (const float*)d_in[0];
    const int*   mk = (const int*)  d_in[1];
    const float* Wq = (const float*)d_in[2];
    const float* bq = (const float*)d_in[3];
    const float* Wk = (const float*)d_in[4];
    const float* bk = (const float*)d_in[5];
    const float* Wv = (const float*)d_in[6];
    const float* bv = (const float*)d_in[7];

    float* out   = (float*)d_out;
    float* out_S = out;                              // [B, S, D]
    float* out_W = out + (size_t)BATCH * SEQ * DIM;  // [B, S, S]
    const float scale = 1.0f / sqrtf((float)DIM);

    cudaFuncSetAttribute(qk_proj_kernel, cudaFuncAttributeMaxDynamicSharedMemorySize, SMEM_BYTES);
    cudaFuncSetAttribute(v_proj_kernel,  cudaFuncAttributeMaxDynamicSharedMemorySize, SMEM_BYTES);
    cudaFuncSetAttribute(scores_kernel,  cudaFuncAttributeMaxDynamicSharedMemorySize, SMEM_BYTES);
    cudaFuncSetAttribute(out_kernel,     cudaFuncAttributeMaxDynamicSharedMemorySize, SMEM_BYTES);

    __half *wth;
    cudaGetSymbolAddress((void**)&wth, g_Wth);

    // One-time infra: streams + per-batch events (no timing -> capturable).
    static cudaStream_t s_v = nullptr, s_sm = nullptr;
    static cudaEvent_t e_fork = nullptr, e_vdone = nullptr;
    static cudaEvent_t e_sc[BATCH], e_sm[BATCH];
    if (s_v == nullptr) {
        cudaStreamCreateWithFlags(&s_v, cudaStreamNonBlocking);
        cudaStreamCreateWithFlags(&s_sm, cudaStreamNonBlocking);
        cudaEventCreateWithFlags(&e_fork, cudaEventDisableTiming);
        cudaEventCreateWithFlags(&e_vdone, cudaEventDisableTiming);
        for (int b = 0; b < BATCH; b++) {
            cudaEventCreateWithFlags(&e_sc[b], cudaEventDisableTiming);
            cudaEventCreateWithFlags(&e_sm[b], cudaEventDisableTiming);
        }
    }

    cvt_x_kernel<<<MROWS * DIM / 4 / 256, 256>>>(X);
    cvt_w_kernel<<<dim3(DIM * DIM / 4 / 256, 1, 3), 256>>>(Wq, Wk, Wv);

    // Fork v_proj (needs only cvt outputs); joined before out(0).
    cudaEventRecord(e_fork, 0);
    cudaStreamWaitEvent(s_v, e_fork, 0);
    v_proj_kernel<<<dim3(128, 4, 1), 256, SMEM_BYTES, s_v>>>(bv);
    cudaEventRecord(e_vdone, s_v);

    qk_proj_kernel<<<dim3(4, 128, 2), 256, SMEM_BYTES>>>(bq, bk);

    // Per-batch scores on stream0; softmax(b) overlapped on s_sm.
    for (int b = 0; b < BATCH; b++) {
        scores_kernel<<<dim3(16, 16, 1), 256, SMEM_BYTES>>>(mk, out_W, scale, b);
        cudaEventRecord(e_sc[b], 0);
        cudaStreamWaitEvent(s_sm, e_sc[b], 0);
        softmax_kernel<<<SEQ, 256, 0, s_sm>>>(out_W, wth, b);
        cudaEventRecord(e_sm[b], s_sm);
    }

    // out(b) on stream0: waits its softmax; tensor work stays serialized on one stream.
    cudaStreamWaitEvent(0, e_vdone, 0);
    for (int b = 0; b < BATCH; b++) {
        cudaStreamWaitEvent(0, e_sm[b], 0);
        out_kernel<<<dim3(4, 16, 1), 256, SMEM_BYTES>>>(out_S, b);
    }
}

// round 15
// speedup vs baseline: 1.5584x; 1.5584x over previous
#include <cuda_runtime.h>
#include <cuda_fp16.h>
#include <cstdint>
#include <cmath>

#define BATCH 8
#define SEQ   2048
#define DIM   512
#define MROWS (BATCH * SEQ)   // 16384

// -------- fp16 scratch (allocation-free) --------
__device__ __half g_Xh[MROWS * DIM];
__device__ __half g_Wqh[DIM * DIM];
__device__ __half g_Wkh[DIM * DIM];
__device__ __half g_Wvh[DIM * DIM];
__device__ __half g_Qh[MROWS * DIM];
__device__ __half g_Kh[MROWS * DIM];
__device__ __half g_Vth[BATCH * DIM * SEQ];
__device__ __half g_Wth[(size_t)BATCH * SEQ * SEQ];

// -------- tiling --------
#define BK 64
#define TILE_B  16384                       // 128 rows x 64 f16 (128 B/row)
#define STAGES  3
#define STAGE_B (2 * TILE_B)                // A + B
#define SMEM_BYTES (STAGES * STAGE_B)       // 98304
#define OFF_B   16384

// ================= PTX helpers =================
__device__ __forceinline__ uint32_t smem_u32(const void* p) {
    uint32_t a;
    asm("{ .reg .u64 t; cvta.to.shared.u64 t, %1; cvt.u32.u64 %0, t; }" : "=r"(a) : "l"(p));
    return a;
}
__device__ __forceinline__ void cp16(uint32_t dst, const void* src) {
    asm volatile("cp.async.cg.shared.global [%0], [%1], 16;" :: "r"(dst), "l"(src));
}
#define CP_COMMIT() asm volatile("cp.async.commit_group;" ::: "memory")
#define CP_WAIT1()  asm volatile("cp.async.wait_group 1;" ::: "memory")

__device__ __forceinline__ void ldm4(uint32_t* d, uint32_t addr) {
    asm volatile("ldmatrix.sync.aligned.m8n8.x4.shared.b16 {%0,%1,%2,%3}, [%4];"
        : "=r"(d[0]), "=r"(d[1]), "=r"(d[2]), "=r"(d[3]) : "r"(addr));
}
__device__ __forceinline__ void mma16(float* d, const uint32_t* a, uint32_t b0, uint32_t b1) {
    asm volatile("mma.sync.aligned.m16n8k16.row.col.f32.f16.f16.f32 "
        "{%0,%1,%2,%3}, {%4,%5,%6,%7}, {%8,%9}, {%0,%1,%2,%3};"
        : "+f"(d[0]), "+f"(d[1]), "+f"(d[2]), "+f"(d[3])
        : "r"(a[0]), "r"(a[1]), "r"(a[2]), "r"(a[3]), "r"(b0), "r"(b1));
}

// 128x64 f16 tile: row r at r*128; chunk c rotated: r*128 + ((c+r)&7)*16.
__device__ __forceinline__ uint32_t tile_addr(uint32_t base, int r, int c) {
    return base + (uint32_t)((r << 7) + ((((c + r) & 7)) << 4));
}

// Producer: 128x64 f16 tile, 1024 chunks, 4 per thread.
__device__ __forceinline__ void load_tile(uint32_t sdst, const __half* __restrict__ src,
                                          int ld, int kt, int tid)
{
    #pragma unroll
    for (int i = 0; i < 4; i++) {
        int ch = tid + i * 256;
        int r = ch >> 3, c = ch & 7;
        cp16(tile_addr(sdst, r, c), src + (size_t)r * ld + kt + c * 8);
    }
}

// ================= GEMM mainloop (BK=64, 3 stages) =================
__device__ __forceinline__ void gemm1_main(
    const __half* __restrict__ Ah, int lda,
    const __half* __restrict__ Bh, int ldb,
    int ktot, float (&acc)[2][8][4], char* smem, int tid)
{
    const int wid = tid >> 5, lane = tid & 31;
    const int wm = (wid & 3) * 32, wn = (wid >> 2) * 64;
    const int q = lane >> 3;
    const int lrow = (lane & 7) + (q & 1) * 8;
    const int qc = q >> 1;
    const uint32_t sbase = smem_u32(smem);
    const int NK = ktot / BK;

    int pf = 0, wrs = 0;
    #pragma unroll
    for (int s = 0; s < STAGES - 1; s++) {
        if (pf < NK) {
            uint32_t sp = sbase + (uint32_t)wrs * STAGE_B;
            load_tile(sp, Ah, lda, pf * BK, tid);
            load_tile(sp + OFF_B, Bh, ldb, pf * BK, tid);
            CP_COMMIT();
            pf++; wrs = (wrs == STAGES - 1) ? 0 : wrs + 1;
        }
    }

    int rds = 0;
    for (int kb = 0; kb < NK; kb++) {
        CP_WAIT1();
        __syncthreads();
        const uint32_t st = sbase + (uint32_t)rds * STAGE_B;
        rds = (rds == STAGES - 1) ? 0 : rds + 1;

        if (pf < NK) {
            uint32_t sp = sbase + (uint32_t)wrs * STAGE_B;
            load_tile(sp, Ah, lda, pf * BK, tid);
            load_tile(sp + OFF_B, Bh, ldb, pf * BK, tid);
            CP_COMMIT();
            pf++; wrs = (wrs == STAGES - 1) ? 0 : wrs + 1;
        } else {
            CP_COMMIT();
        }

        #pragma unroll
        for (int ks = 0; ks < 4; ks++) {
            const int c = 2 * ks + qc;
            uint32_t ah[2][4];
            #pragma unroll
            for (int mt = 0; mt < 2; mt++)
                ldm4(ah[mt], tile_addr(st, wm + mt * 16 + lrow, c));
            uint32_t bh[4][4];
            #pragma unroll
            for (int nb = 0; nb < 4; nb++)
                ldm4(bh[nb], tile_addr(st + OFF_B, wn + nb * 16 + lrow, c));
            #pragma unroll
            for (int mt = 0; mt < 2; mt++)
                #pragma unroll
                for (int nb = 0; nb < 4; nb++) {
                    mma16(acc[mt][nb * 2 + 0], ah[mt], bh[nb][0], bh[nb][2]);
                    mma16(acc[mt][nb * 2 + 1], ah[mt], bh[nb][1], bh[nb][3]);
                }
        }
        // no trailing sync: top-of-loop barrier provides the WAR guarantee.
    }
}

// ================= kernels =================
// Combined fp32 -> fp16 converter: blocks [0, 8192) convert X, then 3x256 blocks for W.
#define XBLKS (MROWS * DIM / 4 / 256)   // 8192
#define WBLKS (DIM * DIM / 4 / 256)     // 256
__global__ __launch_bounds__(256) void cvt_all_kernel(
    const float* __restrict__ X,
    const float* __restrict__ Wq, const float* __restrict__ Wk, const float* __restrict__ Wv)
{
    int blk = blockIdx.x;
    const float* src;
    __half* dst;
    int i;
    if (blk < XBLKS) {
        src = X; dst = g_Xh; i = blk * 256 + threadIdx.x;
    } else {
        int w = (blk - XBLKS) / WBLKS;
        src = w == 0 ? Wq : (w == 1 ? Wk : Wv);
        dst = w == 0 ? g_Wqh : (w == 1 ? g_Wkh : g_Wvh);
        i = ((blk - XBLKS) % WBLKS) * 256 + threadIdx.x;
    }
    float4 v = ((const float4*)src)[i];
    ((__half2*)dst)[i * 2]     = __halves2half2(__float2half_rn(v.x), __float2half_rn(v.y));
    ((__half2*)dst)[i * 2 + 1] = __halves2half2(__float2half_rn(v.z), __float2half_rn(v.w));
}

// Q/K projection (Xh·Wh + b) -> fp16
__global__ __launch_bounds__(256, 2) void qk_proj_kernel(
    const float* __restrict__ bq, const float* __restrict__ bk)
{
    extern __shared__ char smem[];
    const int tid = threadIdx.x, wid = tid >> 5, lane = tid & 31;
    const int g = lane >> 2, tg = lane & 3;
    const int m0 = blockIdx.y * 128, n0 = blockIdx.x * 128;
    const bool isk = blockIdx.z != 0;
    const __half* Wh = isk ? g_Wkh : g_Wqh;
    const float* bias = isk ? bk : bq;
    __half* Oh = isk ? g_Kh : g_Qh;

    float acc[2][8][4] = {};
    gemm1_main(g_Xh + (size_t)m0 * DIM, DIM, Wh + (size_t)n0 * DIM, DIM,
               DIM, acc, smem, tid);

    const int wm = (wid & 3) * 32, wn = (wid >> 2) * 64;
    #pragma unroll
    for (int mt = 0; mt < 2; mt++) {
        int m = m0 + wm + mt * 16 + g;
        #pragma unroll
        for (int nt = 0; nt < 8; nt++) {
            int n = n0 + wn + nt * 8 + tg * 2;
            float b0 = bias[n], b1 = bias[n + 1];
            *(__half2*)&Oh[(size_t)m * DIM + n] =
                __halves2half2(__float2half_rn(acc[mt][nt][0] + b0),
                               __float2half_rn(acc[mt][nt][1] + b1));
            *(__half2*)&Oh[(size_t)(m + 8) * DIM + n] =
                __halves2half2(__float2half_rn(acc[mt][nt][2] + b0),
                               __float2half_rn(acc[mt][nt][3] + b1));
        }
    }
}

// V projection transposed (Wvh·Xh + bv) -> Vt fp16
__global__ __launch_bounds__(256, 2) void v_proj_kernel(const float* __restrict__ bv)
{
    extern __shared__ char smem[];
    const int tid = threadIdx.x, wid = tid >> 5, lane = tid & 31;
    const int g = lane >> 2, tg = lane & 3;
    const int m0 = blockIdx.y * 128, n0 = blockIdx.x * 128;

    float acc[2][8][4] = {};
    gemm1_main(g_Wvh + (size_t)m0 * DIM, DIM, g_Xh + (size_t)n0 * DIM, DIM,
               DIM, acc, smem, tid);

    const int wm = (wid & 3) * 32, wn = (wid >> 2) * 64;
    const int b = n0 >> 11;
    #pragma unroll
    for (int mt = 0; mt < 2; mt++) {
        int e = m0 + wm + mt * 16 + g;
        float be0 = bv[e], be1 = bv[e + 8];
        #pragma unroll
        for (int nt = 0; nt < 8; nt++) {
            int t = n0 + wn + nt * 8 + tg * 2;
            int s = t & 2047;
            __half2 h = __halves2half2(__float2half_rn(acc[mt][nt][0] + be0),
                                       __float2half_rn(acc[mt][nt][1] + be0));
            *(__half2*)&g_Vth[((size_t)b * DIM + e) * SEQ + s] = h;
            h = __halves2half2(__float2half_rn(acc[mt][nt][2] + be1),
                               __float2half_rn(acc[mt][nt][3] + be1));
            *(__half2*)&g_Vth[((size_t)b * DIM + e + 8) * SEQ + s] = h;
        }
    }
}

// scores (Qh·Kh; masked, fp32 out)
__global__ __launch_bounds__(256, 2) void scores_kernel(
    const int* __restrict__ mask, float* __restrict__ out_w, float scale)
{
    extern __shared__ char smem[];
    const int tid = threadIdx.x, wid = tid >> 5, lane = tid & 31;
    const int g = lane >> 2, tg = lane & 3;
    const int b = blockIdx.z;
    const int m0 = blockIdx.y * 128, n0 = blockIdx.x * 128;
    const size_t qoff = ((size_t)b * SEQ + m0) * DIM;
    const size_t koff = ((size_t)b * SEQ + n0) * DIM;

    float acc[2][8][4] = {};
    gemm1_main(g_Qh + qoff, DIM, g_Kh + koff, DIM, DIM, acc, smem, tid);

    const int wm = (wid & 3) * 32, wn = (wid >> 2) * 64;
    const size_t base = (size_t)b * SEQ * SEQ;
    #pragma unroll
    for (int mt = 0; mt < 2; mt++) {
        int qq = m0 + wm + mt * 16 + g;
        #pragma unroll
        for (int nt = 0; nt < 8; nt++) {
            int n = n0 + wn + nt * 8 + tg * 2;
            size_t i0 = base + (size_t)qq * SEQ + n;
            size_t i1 = base + (size_t)(qq + 8) * SEQ + n;
            int2 mk0 = *(const int2*)&mask[i0];
            int2 mk1 = *(const int2*)&mask[i1];
            *(float2*)&out_w[i0] = make_float2(mk0.x ? acc[mt][nt][0] * scale : -1e9f,
                                              mk0.y ? acc[mt][nt][1] * scale : -1e9f);
            *(float2*)&out_w[i1] = make_float2(mk1.x ? acc[mt][nt][2] * scale : -1e9f,
                                              mk1.y ? acc[mt][nt][3] * scale : -1e9f);
        }
    }
}

// softmax in place (fp32) + fp16 copy
__global__ __launch_bounds__(256) void softmax_kernel(
    float* __restrict__ W, __half* __restrict__ Wh)
{
    const size_t rowb = (size_t)blockIdx.x * SEQ;
    float4* p = (float4*)(W + rowb);
    __half2* ph = (__half2*)(Wh + rowb);
    const int tid = threadIdx.x;

    float4 v[2];
    float m = -INFINITY;
    #pragma unroll
    for (int i = 0; i < 2; i++) {
        v[i] = p[tid + i * 256];
        m = fmaxf(m, fmaxf(fmaxf(v[i].x, v[i].y), fmaxf(v[i].z, v[i].w)));
    }
    __shared__ float red[256];
    red[tid] = m; __syncthreads();
    #pragma unroll
    for (int s = 128; s > 0; s >>= 1) { if (tid < s) red[tid] = fmaxf(red[tid], red[tid + s]); __syncthreads(); }
    m = red[0]; __syncthreads();

    float sum = 0.0f;
    #pragma unroll
    for (int i = 0; i < 2; i++) {
        v[i].x = __expf(v[i].x - m); v[i].y = __expf(v[i].y - m);
        v[i].z = __expf(v[i].z - m); v[i].w = __expf(v[i].w - m);
        sum += v[i].x + v[i].y + v[i].z + v[i].w;
    }
    red[tid] = sum; __syncthreads();
    #pragma unroll
    for (int s = 128; s > 0; s >>= 1) { if (tid < s) red[tid] += red[tid + s]; __syncthreads(); }
    float inv = 1.0f / red[0];

    #pragma unroll
    for (int i = 0; i < 2; i++) {
        int j = tid + i * 256;
        v[i].x *= inv; v[i].y *= inv; v[i].z *= inv; v[i].w *= inv;
        p[j] = v[i];
        ph[j * 2]     = __halves2half2(__float2half_rn(v[i].x), __float2half_rn(v[i].y));
        ph[j * 2 + 1] = __halves2half2(__float2half_rn(v[i].z), __float2half_rn(v[i].w));
    }
}

// out: C[q][d] = Wgt_h[q]·Vt_h[d]
__global__ __launch_bounds__(256, 2) void out_kernel(float* __restrict__ O)
{
    extern __shared__ char smem[];
    const int tid = threadIdx.x, wid = tid >> 5, lane = tid & 31;
    const int g = lane >> 2, tg = lane & 3;
    const int b = blockIdx.z;
    const int m0 = blockIdx.y * 128, n0 = blockIdx.x * 128;
    const size_t aoff = (size_t)b * SEQ * SEQ + (size_t)m0 * SEQ;
    const size_t boff = (size_t)b * DIM * SEQ + (size_t)n0 * SEQ;

    float acc[2][8][4] = {};
    gemm1_main(g_Wth + aoff, SEQ, g_Vth + boff, SEQ, SEQ, acc, smem, tid);

    const int wm = (wid & 3) * 32, wn = (wid >> 2) * 64;
    float* Ob = O + (size_t)b * SEQ * DIM;
    #pragma unroll
    for (int mt = 0; mt < 2; mt++) {
        int qq = m0 + wm + mt * 16 + g;
        #pragma unroll
        for (int nt = 0; nt < 8; nt++) {
            int n = n0 + wn + nt * 8 + tg * 2;
            *(float2*)&Ob[(size_t)qq * DIM + n] = make_float2(acc[mt][nt][0], acc[mt][nt][1]);
            *(float2*)&Ob[(size_t)(qq + 8) * DIM + n] = make_float2(acc[mt][nt][2], acc[mt][nt][3]);
        }
    }
}

// ================= launch =================
extern "C" void kernel_launch(void* const* d_in, const int* in_sizes, int n_in,
                              void* d_out, int out_size)
{
    const float* X  = (const float*)d_in[0];
    const int*   mk = (const int*)  d_in[1];
    const float* Wq = (const float*)d_in[2];
    const float* bq = (const float*)d_in[3];
    const float* Wk = (const float*)d_in[4];
    const float* bk = (const float*)d_in[5];
    const float* Wv = (const float*)d_in[6];
    const float* bv = (const float*)d_in[7];

    float* out   = (float*)d_out;
    float* out_S = out;                              // [B, S, D]
    float* out_W = out + (size_t)BATCH * SEQ * DIM;  // [B, S, S]
    const float scale = 1.0f / sqrtf((float)DIM);

    cudaFuncSetAttribute(qk_proj_kernel, cudaFuncAttributeMaxDynamicSharedMemorySize, SMEM_BYTES);
    cudaFuncSetAttribute(v_proj_kernel,  cudaFuncAttributeMaxDynamicSharedMemorySize, SMEM_BYTES);
    cudaFuncSetAttribute(scores_kernel,  cudaFuncAttributeMaxDynamicSharedMemorySize, SMEM_BYTES);
    cudaFuncSetAttribute(out_kernel,     cudaFuncAttributeMaxDynamicSharedMemorySize, SMEM_BYTES);

    __half *wth;
    cudaGetSymbolAddress((void**)&wth, g_Wth);

    // One-time infra (no timing events -> graph-capturable).
    static cudaStream_t s_v = nullptr;
    static cudaEvent_t e_fork = nullptr, e_join = nullptr;
    if (s_v == nullptr) {
        cudaStreamCreateWithFlags(&s_v, cudaStreamNonBlocking);
        cudaEventCreateWithFlags(&e_fork, cudaEventDisableTiming);
        cudaEventCreateWithFlags(&e_join, cudaEventDisableTiming);
    }

    cvt_all_kernel<<<XBLKS + 3 * WBLKS, 256>>>(X, Wq, Wk, Wv);

    // Fork: v_proj runs concurrently with qk_proj/scores (depends only on cvt outputs).
    cudaEventRecord(e_fork, 0);
    cudaStreamWaitEvent(s_v, e_fork, 0);
    v_proj_kernel<<<dim3(128, 4, 1), 256, SMEM_BYTES, s_v>>>(bv);
    cudaEventRecord(e_join, s_v);

    qk_proj_kernel<<<dim3(4, 128, 2), 256, SMEM_BYTES>>>(bq, bk);
    scores_kernel<<<dim3(16, 16, 8), 256, SMEM_BYTES>>>(mk, out_W, scale);
    softmax_kernel<<<BATCH * SEQ, 256>>>(out_W, wth);

    // Join: out consumes g_Vth.
    cudaStreamWaitEvent(0, e_join, 0);
    out_kernel<<<dim3(4, 16, 8), 256, SMEM_BYTES>>>(out_S);
}